// round 3
// baseline (speedup 1.0000x reference)
#include <cuda_runtime.h>
#include <cstdint>
#include <math.h>

#define NTOK 8192
#define CDIM 64
#define NEXP 16
#define CAP  640
#define NEC  ((size_t)NTOK * NEXP * CAP)       /* 83,886,080 elements */
#define SCALAR_OFF (2 * NEC)                   /* z, aux, std */
#define LOGITS_OFF (2 * NEC + 3)

// ---------------- scratch (no allocs allowed) ----------------
__device__ float              g_probs[NTOK * NEXP];
__device__ float              g_lse2[NTOK];
__device__ unsigned long long g_keys[NTOK];
__device__ int                g_expert[NTOK];
__device__ int                g_pos[NTOK];

// ---------------- kernel 0: zero-fill (replaces cudaMemsetAsync) ----------------
// 2*NEC floats = 41,943,040 float4 stores. Grid-stride, 128-bit stores.
__global__ void __launch_bounds__(256) fill_kernel(float4* __restrict__ out) {
    const size_t total = (2 * NEC) / 4;  // float4 count
    size_t i = (size_t)blockIdx.x * blockDim.x + threadIdx.x;
    const size_t stride = (size_t)gridDim.x * blockDim.x;
    const float4 z = make_float4(0.f, 0.f, 0.f, 0.f);
    for (; i < total; i += stride) out[i] = z;
}

// ---------------- kernel 1: pool + gate + softmax ----------------
// one block (64 threads) per token
__global__ void gating_kernel(const float* __restrict__ X,
                              const float* __restrict__ Wg,
                              const float* __restrict__ bg,
                              float* __restrict__ out_logits) {
    __shared__ float pooled[CDIM];
    __shared__ float lg[NEXP];
    int n = blockIdx.x;
    int c = threadIdx.x;  // 0..63

    // channel-mean over 8x8 spatial
    const float4* xp = (const float4*)(X + (size_t)n * (CDIM * 64) + (size_t)c * 64);
    float s = 0.f;
#pragma unroll
    for (int i = 0; i < 16; i++) {
        float4 v = xp[i];
        s += (v.x + v.y) + (v.z + v.w);
    }
    pooled[c] = s * (1.f / 64.f);
    __syncthreads();

    if (c < NEXP) {
        float d = bg[c];
#pragma unroll
        for (int k = 0; k < CDIM; k++) d += pooled[k] * Wg[k * NEXP + c];
        float l = d * (1.f / 1.5f);
        l = fminf(10.f, fmaxf(-10.f, l));
        lg[c] = l;
        out_logits[(size_t)n * NEXP + c] = l;
    }
    __syncthreads();

    if (c < 32) {  // warp 0 does softmax/argmax; lanes 0..15 carry data
        float v = (c < 16) ? lg[c] : -3.0e38f;
        float m = v;
        int   mi = c;
#pragma unroll
        for (int o = 8; o; o >>= 1) {
            float om = __shfl_xor_sync(0xffffffffu, m, o);
            int   oi = __shfl_xor_sync(0xffffffffu, mi, o);
            if (om > m || (om == m && oi < mi)) { m = om; mi = oi; }
        }
        float ev = (c < 16) ? expf(v - m) : 0.f;
        float sum = ev;
#pragma unroll
        for (int o = 8; o; o >>= 1) sum += __shfl_xor_sync(0xffffffffu, sum, o);
        if (c < 16) g_probs[n * NEXP + c] = ev / sum;
        if (c == 0) {
            float lse = m + logf(sum);
            g_lse2[n] = lse * lse;
            float pe = 1.f / sum;  // top-1 prob: exp(0)/sum
            g_expert[n] = mi;
            // sortable key: expert (4b) | prob bits (32b, positive float => monotonic) | 8191-n (stable tie-break)
            unsigned long long key = ((unsigned long long)mi << 45)
                                   | ((unsigned long long)__float_as_uint(pe) << 13)
                                   | (unsigned long long)(8191 - n);
            g_keys[n] = key;
        }
    }
}

// ---------------- kernel 2: per-expert rank (capacity position) ----------------
// 128 blocks x 256 threads; each warp handles 8 tokens; brute-force count over all keys
__global__ void rank_kernel() {
    __shared__ unsigned long long sk[4096];
    int t = threadIdx.x;
    int warp = t >> 5, lane = t & 31;
    int base = blockIdx.x * 64 + warp * 8;

    unsigned long long mykey[8], hi[8];
    int cnt[8];
#pragma unroll
    for (int q = 0; q < 8; q++) {
        mykey[q] = g_keys[base + q];
        hi[q] = ((mykey[q] >> 45) + 1ull) << 45;
        cnt[q] = 0;
    }
    for (int half = 0; half < 2; half++) {
        __syncthreads();
        for (int i = t; i < 4096; i += 256) sk[i] = g_keys[half * 4096 + i];
        __syncthreads();
        for (int j = lane; j < 4096; j += 32) {
            unsigned long long k = sk[j];
#pragma unroll
            for (int q = 0; q < 8; q++)
                cnt[q] += (int)((k > mykey[q]) & (k < hi[q]));
        }
    }
#pragma unroll
    for (int q = 0; q < 8; q++) {
        int csum = cnt[q];
#pragma unroll
        for (int o = 16; o; o >>= 1) csum += __shfl_xor_sync(0xffffffffu, csum, o);
        if (lane == 0) g_pos[base + q] = csum;
    }
}

// ---------------- kernel 3: scatter the one-hots ----------------
__global__ void scatter_kernel(float* __restrict__ out) {
    int n = blockIdx.x * blockDim.x + threadIdx.x;
    if (n >= NTOK) return;
    int pos = g_pos[n];
    if (pos < CAP) {
        size_t off = ((size_t)n * NEXP + g_expert[n]) * CAP + pos;
        out[off] = 1.f;        // dispatch
        out[NEC + off] = 1.f;  // combine (== dispatch for top-1 routing)
    }
}

// ---------------- kernel 4: scalar losses (deterministic reductions) ----------------
__global__ void finalize_kernel(const float* __restrict__ logits,
                                float* __restrict__ scal) {
    __shared__ float part[1024];
    __shared__ int   hist[NEXP];
    __shared__ float cs[NEXP];
    __shared__ float res_z, res_s1, res_s2;
    int t = threadIdx.x;

    if (t < NEXP) hist[t] = 0;
    __syncthreads();

    // per-expert surviving-token counts (integer atomics: deterministic)
    for (int i = t; i < NTOK; i += 1024)
        if (g_pos[i] < CAP) atomicAdd(&hist[g_expert[i]], 1);

    // per-expert prob column sums: thread t only ever touches column t&15
    float cp = 0.f;
    for (int i = t; i < NTOK * NEXP; i += 1024) cp += g_probs[i];
    part[t] = cp;
    __syncthreads();
    if (t < NEXP) {
        float s = 0.f;
        for (int k = t; k < 1024; k += NEXP) s += part[k];
        cs[t] = s;
    }
    __syncthreads();

    // z-loss: sum of lse^2
    float sz = 0.f;
    for (int i = t; i < NTOK; i += 1024) sz += g_lse2[i];
    part[t] = sz;
    __syncthreads();
    for (int o = 512; o; o >>= 1) { if (t < o) part[t] += part[t + o]; __syncthreads(); }
    if (t == 0) res_z = part[0];
    __syncthreads();

    // logits sum & sum of squares for std
    float s1 = 0.f, s2 = 0.f;
    for (int i = t; i < NTOK * NEXP; i += 1024) {
        float v = logits[i];
        s1 += v; s2 += v * v;
    }
    part[t] = s1;
    __syncthreads();
    for (int o = 512; o; o >>= 1) { if (t < o) part[t] += part[t + o]; __syncthreads(); }
    if (t == 0) res_s1 = part[0];
    __syncthreads();
    part[t] = s2;
    __syncthreads();
    for (int o = 512; o; o >>= 1) { if (t < o) part[t] += part[t + o]; __syncthreads(); }
    if (t == 0) res_s2 = part[0];
    __syncthreads();

    if (t == 0) {
        scal[0] = res_z / (float)NTOK;  // z_loss
        float aux = 0.f;
        for (int e = 0; e < NEXP; e++)
            aux += ((float)hist[e] / (float)NTOK) * (cs[e] / (float)NTOK);
        scal[1] = aux * (float)NEXP;    // aux_loss
        float inv = 1.f / (float)(NTOK * NEXP);
        float mean = res_s1 * inv;
        float var = res_s2 * inv - mean * mean;
        scal[2] = sqrtf(fmaxf(var, 0.f));  // logits_std
    }
}

// ---------------- launch: fork custom fill onto a side stream ----------------
extern "C" void kernel_launch(void* const* d_in, const int* in_sizes, int n_in,
                              void* d_out, int out_size) {
    const float* X  = (const float*)d_in[0];
    const float* Wg = (const float*)d_in[1];
    const float* bg = (const float*)d_in[2];
    float* out = (float*)d_out;

    // One-time host-side resource creation (streams/events: no device memory).
    static cudaStream_t s_side = nullptr;
    static cudaEvent_t  ev_start = nullptr, ev_rank = nullptr, ev_done = nullptr;
    if (s_side == nullptr) {
        cudaStreamCreateWithFlags(&s_side, cudaStreamNonBlocking);
        cudaEventCreateWithFlags(&ev_start, cudaEventDisableTiming);
        cudaEventCreateWithFlags(&ev_rank,  cudaEventDisableTiming);
        cudaEventCreateWithFlags(&ev_done,  cudaEventDisableTiming);
    }

    // Fork: side stream zeros the 672MB dispatch+combine region (custom
    // vectorized fill) while the capture stream runs the compute chain.
    cudaEventRecord(ev_start, 0);
    cudaStreamWaitEvent(s_side, ev_start, 0);
    fill_kernel<<<8192, 256, 0, s_side>>>((float4*)out);

    // Compute chain on capture stream (writes logits + scalars at out tail,
    // outside the fill range).
    gating_kernel<<<NTOK, 64>>>(X, Wg, bg, out + LOGITS_OFF);
    rank_kernel<<<128, 256>>>();
    cudaEventRecord(ev_rank, 0);
    finalize_kernel<<<1, 1024>>>(out + LOGITS_OFF, out + SCALAR_OFF);

    // Side stream: once ranks are known AND zeroing finished, scatter the ones.
    cudaStreamWaitEvent(s_side, ev_rank, 0);
    scatter_kernel<<<(NTOK + 255) / 256, 256, 0, s_side>>>(out);
    cudaEventRecord(ev_done, s_side);

    // Join back onto the capture stream.
    cudaStreamWaitEvent(0, ev_done, 0);
}

// round 4
// speedup vs baseline: 1.1145x; 1.1145x over previous
#include <cuda_runtime.h>
#include <cstdint>
#include <math.h>

#define NTOK 8192
#define CDIM 64
#define NEXP 16
#define CAP  640
#define NEC  ((size_t)NTOK * NEXP * CAP)       /* 83,886,080 elements */
#define SCALAR_OFF (2 * NEC)                   /* z, aux, std */
#define LOGITS_OFF (2 * NEC + 3)

// ---------------- scratch (no allocs allowed) ----------------
__device__ float              g_probs[NTOK * NEXP];
__device__ float              g_lse2[NTOK];
__device__ unsigned long long g_keys[NTOK];
__device__ int                g_expert[NTOK];
__device__ int                g_pos[NTOK];

// ---------------- kernel 1: pool + gate + softmax ----------------
// one block (64 threads) per token; pure-read phase
__global__ void gating_kernel(const float* __restrict__ X,
                              const float* __restrict__ Wg,
                              const float* __restrict__ bg,
                              float* __restrict__ out_logits) {
    __shared__ float pooled[CDIM];
    __shared__ float lg[NEXP];
    int n = blockIdx.x;
    int c = threadIdx.x;  // 0..63

    const float4* xp = (const float4*)(X + (size_t)n * (CDIM * 64) + (size_t)c * 64);
    float s = 0.f;
#pragma unroll
    for (int i = 0; i < 16; i++) {
        float4 v = xp[i];
        s += (v.x + v.y) + (v.z + v.w);
    }
    pooled[c] = s * (1.f / 64.f);
    __syncthreads();

    if (c < NEXP) {
        float d = bg[c];
#pragma unroll
        for (int k = 0; k < CDIM; k++) d += pooled[k] * Wg[k * NEXP + c];
        float l = d * (1.f / 1.5f);
        l = fminf(10.f, fmaxf(-10.f, l));
        lg[c] = l;
        out_logits[(size_t)n * NEXP + c] = l;
    }
    __syncthreads();

    if (c < 32) {  // warp 0: softmax/argmax; lanes 0..15 carry data
        float v = (c < 16) ? lg[c] : -3.0e38f;
        float m = v;
        int   mi = c;
#pragma unroll
        for (int o = 8; o; o >>= 1) {
            float om = __shfl_xor_sync(0xffffffffu, m, o);
            int   oi = __shfl_xor_sync(0xffffffffu, mi, o);
            if (om > m || (om == m && oi < mi)) { m = om; mi = oi; }
        }
        float ev = (c < 16) ? expf(v - m) : 0.f;
        float sum = ev;
#pragma unroll
        for (int o = 8; o; o >>= 1) sum += __shfl_xor_sync(0xffffffffu, sum, o);
        if (c < 16) g_probs[n * NEXP + c] = ev / sum;
        if (c == 0) {
            float lse = m + logf(sum);
            g_lse2[n] = lse * lse;
            float pe = 1.f / sum;  // top-1 prob = exp(0)/sum
            g_expert[n] = mi;
            // key: expert (4b) | prob bits (monotonic for positive floats) | 8191-n (stable tie-break)
            unsigned long long key = ((unsigned long long)mi << 45)
                                   | ((unsigned long long)__float_as_uint(pe) << 13)
                                   | (unsigned long long)(8191 - n);
            g_keys[n] = key;
        }
    }
}

// ---------------- kernel 2: per-expert rank (capacity position) ----------------
__global__ void rank_kernel() {
    __shared__ unsigned long long sk[4096];
    int t = threadIdx.x;
    int warp = t >> 5, lane = t & 31;
    int base = blockIdx.x * 64 + warp * 8;

    unsigned long long mykey[8], hi[8];
    int cnt[8];
#pragma unroll
    for (int q = 0; q < 8; q++) {
        mykey[q] = g_keys[base + q];
        hi[q] = ((mykey[q] >> 45) + 1ull) << 45;
        cnt[q] = 0;
    }
    for (int half = 0; half < 2; half++) {
        __syncthreads();
        for (int i = t; i < 4096; i += 256) sk[i] = g_keys[half * 4096 + i];
        __syncthreads();
        for (int j = lane; j < 4096; j += 32) {
            unsigned long long k = sk[j];
#pragma unroll
            for (int q = 0; q < 8; q++)
                cnt[q] += (int)((k > mykey[q]) & (k < hi[q]));
        }
    }
#pragma unroll
    for (int q = 0; q < 8; q++) {
        int csum = cnt[q];
#pragma unroll
        for (int o = 16; o; o >>= 1) csum += __shfl_xor_sync(0xffffffffu, csum, o);
        if (lane == 0) g_pos[base + q] = csum;
    }
}

// ---------------- kernel 3: fused write-out (zeros + ones in one pass) ----------
// One block per token; writes the token's dispatch row-block (16*640 floats)
// and combine row-block. Pure-write phase, 672MB total, fully coalesced.
__global__ void __launch_bounds__(256) writeout_kernel(float* __restrict__ out) {
    const int n = blockIdx.x;
    const int t = threadIdx.x;

    // hot element within the token's [NEXP*CAP] slab (or -1 if over capacity)
    int pos = g_pos[n];
    int hot = (pos < CAP) ? (g_expert[n] * CAP + pos) : -1;
    const int hot_v = hot >> 2;      // which float4
    const int hot_e = hot & 3;       // element within it

    float4* dsp = (float4*)(out + (size_t)n * (NEXP * CAP));
    float4* cmb = (float4*)(out + NEC + (size_t)n * (NEXP * CAP));

    const float4 z = make_float4(0.f, 0.f, 0.f, 0.f);
    // NEXP*CAP/4 = 2560 float4 per slab; 256 threads * 10 iters
#pragma unroll
    for (int i = 0; i < 10; i++) {
        int idx = t + i * 256;
        float4 v = z;
        if (hot >= 0 && idx == hot_v) {
            ((float*)&v)[hot_e] = 1.f;
        }
        dsp[idx] = v;
        cmb[idx] = v;   // combine == dispatch for top-1 routing
    }
}

// ---------------- kernel 4: scalar losses (latency-bound; runs overlapped) ----
__global__ void finalize_kernel(const float* __restrict__ logits,
                                float* __restrict__ scal) {
    __shared__ float part[1024];
    __shared__ int   hist[NEXP];
    __shared__ float cs[NEXP];
    __shared__ float res_z, res_s1, res_s2;
    int t = threadIdx.x;

    if (t < NEXP) hist[t] = 0;
    __syncthreads();

    for (int i = t; i < NTOK; i += 1024)
        if (g_pos[i] < CAP) atomicAdd(&hist[g_expert[i]], 1);

    float cp = 0.f;
    for (int i = t; i < NTOK * NEXP; i += 1024) cp += g_probs[i];
    part[t] = cp;
    __syncthreads();
    if (t < NEXP) {
        float s = 0.f;
        for (int k = t; k < 1024; k += NEXP) s += part[k];
        cs[t] = s;
    }
    __syncthreads();

    float sz = 0.f;
    for (int i = t; i < NTOK; i += 1024) sz += g_lse2[i];
    part[t] = sz;
    __syncthreads();
    for (int o = 512; o; o >>= 1) { if (t < o) part[t] += part[t + o]; __syncthreads(); }
    if (t == 0) res_z = part[0];
    __syncthreads();

    float s1 = 0.f, s2 = 0.f;
    for (int i = t; i < NTOK * NEXP; i += 1024) {
        float v = logits[i];
        s1 += v; s2 += v * v;
    }
    part[t] = s1;
    __syncthreads();
    for (int o = 512; o; o >>= 1) { if (t < o) part[t] += part[t + o]; __syncthreads(); }
    if (t == 0) res_s1 = part[0];
    __syncthreads();
    part[t] = s2;
    __syncthreads();
    for (int o = 512; o; o >>= 1) { if (t < o) part[t] += part[t + o]; __syncthreads(); }
    if (t == 0) res_s2 = part[0];
    __syncthreads();

    if (t == 0) {
        scal[0] = res_z / (float)NTOK;
        float aux = 0.f;
        for (int e = 0; e < NEXP; e++)
            aux += ((float)hist[e] / (float)NTOK) * (cs[e] / (float)NTOK);
        scal[1] = aux * (float)NEXP;
        float inv = 1.f / (float)(NTOK * NEXP);
        float mean = res_s1 * inv;
        float var = res_s2 * inv - mean * mean;
        scal[2] = sqrtf(fmaxf(var, 0.f));
    }
}

// ---------------- launch: serial read phase -> serial write phase ----------
// Only the latency-bound finalize overlaps the write phase.
extern "C" void kernel_launch(void* const* d_in, const int* in_sizes, int n_in,
                              void* d_out, int out_size) {
    const float* X  = (const float*)d_in[0];
    const float* Wg = (const float*)d_in[1];
    const float* bg = (const float*)d_in[2];
    float* out = (float*)d_out;

    static cudaStream_t s_side = nullptr;
    static cudaEvent_t  ev_rank = nullptr, ev_fin = nullptr;
    if (s_side == nullptr) {
        cudaStreamCreateWithFlags(&s_side, cudaStreamNonBlocking);
        cudaEventCreateWithFlags(&ev_rank, cudaEventDisableTiming);
        cudaEventCreateWithFlags(&ev_fin,  cudaEventDisableTiming);
    }

    // Phase 1 (pure read): gating + rank
    gating_kernel<<<NTOK, 64>>>(X, Wg, bg, out + LOGITS_OFF);
    rank_kernel<<<128, 256>>>();
    cudaEventRecord(ev_rank, 0);

    // Latency-bound scalar losses overlap the write phase (negligible DRAM use)
    cudaStreamWaitEvent(s_side, ev_rank, 0);
    finalize_kernel<<<1, 1024, 0, s_side>>>(out + LOGITS_OFF, out + SCALAR_OFF);
    cudaEventRecord(ev_fin, s_side);

    // Phase 2 (pure write): fused zero-fill + one-hot scatter, 672MB
    writeout_kernel<<<NTOK, 256>>>(out);

    cudaStreamWaitEvent(0, ev_fin, 0);
}

// round 5
// speedup vs baseline: 1.2842x; 1.1522x over previous
#include <cuda_runtime.h>
#include <cstdint>
#include <math.h>

#define NTOK 8192
#define CDIM 64
#define NEXP 16
#define CAP  640
#define NEC  ((size_t)NTOK * NEXP * CAP)       /* 83,886,080 elements */
#define SCALAR_OFF (2 * NEC)                   /* z, aux, std */
#define LOGITS_OFF (2 * NEC + 3)

// ---------------- scratch (no allocs allowed) ----------------
__device__ float              g_probs[NTOK * NEXP];
__device__ float              g_lse2[NTOK];
__device__ unsigned long long g_keys[NTOK];
__device__ int                g_expert[NTOK];
__device__ int                g_pos[NTOK];
__device__ int                g_bcnt[NEXP];
__device__ unsigned long long g_bkeys[NEXP * NTOK];   // per-expert key buckets (1MB)

// ---------------- kernel 0: zero bucket counters ----------------
__global__ void init_kernel() {
    if (threadIdx.x < NEXP) g_bcnt[threadIdx.x] = 0;
}

// ---------------- kernel 1: pool + gate + softmax + bucket scatter ----------
// one block (64 threads) per token; COALESCED reads + smem transpose
__global__ void gating_kernel(const float* __restrict__ X,
                              const float* __restrict__ Wg,
                              const float* __restrict__ bg,
                              float* __restrict__ out_logits) {
    __shared__ float part[64 * 17];   // [channel][lane-in-channel], padded
    __shared__ float pooled[CDIM];
    __shared__ float lg[NEXP];
    const int n = blockIdx.x;
    const int c = threadIdx.x;  // 0..63

    // Coalesced: warp reads 512B contiguous per LDG round.
    // float4 index f = i*64 + c; channel = f>>4 = i*4 + (c>>4); slot = c&15.
    const float4* xp = (const float4*)(X + (size_t)n * (CDIM * 64));
#pragma unroll
    for (int i = 0; i < 16; i++) {
        float4 v = xp[i * 64 + c];
        part[(i * 4 + (c >> 4)) * 17 + (c & 15)] = (v.x + v.y) + (v.z + v.w);
    }
    __syncthreads();

    float s = 0.f;
#pragma unroll
    for (int j = 0; j < 16; j++) s += part[c * 17 + j];
    pooled[c] = s * (1.f / 64.f);
    __syncthreads();

    if (c < NEXP) {
        float d = bg[c];
#pragma unroll
        for (int k = 0; k < CDIM; k++) d += pooled[k] * Wg[k * NEXP + c];
        float l = d * (1.f / 1.5f);
        l = fminf(10.f, fmaxf(-10.f, l));
        lg[c] = l;
        out_logits[(size_t)n * NEXP + c] = l;
    }
    __syncthreads();

    if (c < 32) {  // warp 0: softmax/argmax; lanes 0..15 carry data
        float v = (c < 16) ? lg[c] : -3.0e38f;
        float m = v;
        int   mi = c;
#pragma unroll
        for (int o = 8; o; o >>= 1) {
            float om = __shfl_xor_sync(0xffffffffu, m, o);
            int   oi = __shfl_xor_sync(0xffffffffu, mi, o);
            if (om > m || (om == m && oi < mi)) { m = om; mi = oi; }
        }
        float ev = (c < 16) ? expf(v - m) : 0.f;
        float sum = ev;
#pragma unroll
        for (int o = 8; o; o >>= 1) sum += __shfl_xor_sync(0xffffffffu, sum, o);
        if (c < 16) g_probs[n * NEXP + c] = ev / sum;
        if (c == 0) {
            float lse = m + logf(sum);
            g_lse2[n] = lse * lse;
            float pe = 1.f / sum;  // top-1 prob = exp(0)/sum
            g_expert[n] = mi;
            // key: expert (4b) | prob bits (monotonic, positive floats) | 8191-n (stable tie-break)
            unsigned long long key = ((unsigned long long)mi << 45)
                                   | ((unsigned long long)__float_as_uint(pe) << 13)
                                   | (unsigned long long)(8191 - n);
            g_keys[n] = key;
            // bucket scatter (order within bucket is irrelevant: rank is
            // recomputed by exact key compares)
            int slot = atomicAdd(&g_bcnt[mi], 1);
            g_bkeys[mi * NTOK + slot] = key;
        }
    }
}

// ---------------- kernel 2: per-expert rank via buckets ----------------
// one warp per token; lanes split the bucket scan (coalesced)
__global__ void rank_kernel() {
    const int warp = threadIdx.x >> 5, lane = threadIdx.x & 31;
    const int n = blockIdx.x * 8 + warp;
    unsigned long long mykey = g_keys[n];
    int e = g_expert[n];
    int m = g_bcnt[e];
    const unsigned long long* bk = g_bkeys + (size_t)e * NTOK;
    int cnt = 0;
    for (int j = lane; j < m; j += 32) cnt += (int)(bk[j] > mykey);
#pragma unroll
    for (int o = 16; o; o >>= 1) cnt += __shfl_xor_sync(0xffffffffu, cnt, o);
    if (lane == 0) g_pos[n] = cnt;
}

// ---------------- kernel 3: fused write-out (zeros + ones, one pass) --------
__global__ void __launch_bounds__(256) writeout_kernel(float* __restrict__ out) {
    const int n = blockIdx.x;
    const int t = threadIdx.x;

    int pos = g_pos[n];
    int hot = (pos < CAP) ? (g_expert[n] * CAP + pos) : -1;
    const int hot_v = hot >> 2;
    const int hot_e = hot & 3;

    float4* dsp = (float4*)(out + (size_t)n * (NEXP * CAP));
    float4* cmb = (float4*)(out + NEC + (size_t)n * (NEXP * CAP));

    const float4 z = make_float4(0.f, 0.f, 0.f, 0.f);
#pragma unroll
    for (int i = 0; i < 10; i++) {
        int idx = t + i * 256;
        float4 v = z;
        if (hot >= 0 && idx == hot_v) ((float*)&v)[hot_e] = 1.f;
        __stcs(&dsp[idx], v);   // streaming (evict-first) stores
        __stcs(&cmb[idx], v);   // combine == dispatch for top-1 routing
    }
}

// ---------------- kernel 4: scalar losses (latency-bound; overlapped) -------
__global__ void finalize_kernel(const float* __restrict__ logits,
                                float* __restrict__ scal) {
    __shared__ float part[1024];
    __shared__ int   hist[NEXP];
    __shared__ float cs[NEXP];
    __shared__ float res_z, res_s1, res_s2;
    int t = threadIdx.x;

    if (t < NEXP) hist[t] = 0;
    __syncthreads();

    for (int i = t; i < NTOK; i += 1024)
        if (g_pos[i] < CAP) atomicAdd(&hist[g_expert[i]], 1);

    float cp = 0.f;
    for (int i = t; i < NTOK * NEXP; i += 1024) cp += g_probs[i];
    part[t] = cp;
    __syncthreads();
    if (t < NEXP) {
        float s = 0.f;
        for (int k = t; k < 1024; k += NEXP) s += part[k];
        cs[t] = s;
    }
    __syncthreads();

    float sz = 0.f;
    for (int i = t; i < NTOK; i += 1024) sz += g_lse2[i];
    part[t] = sz;
    __syncthreads();
    for (int o = 512; o; o >>= 1) { if (t < o) part[t] += part[t + o]; __syncthreads(); }
    if (t == 0) res_z = part[0];
    __syncthreads();

    float s1 = 0.f, s2 = 0.f;
    for (int i = t; i < NTOK * NEXP; i += 1024) {
        float v = logits[i];
        s1 += v; s2 += v * v;
    }
    part[t] = s1;
    __syncthreads();
    for (int o = 512; o; o >>= 1) { if (t < o) part[t] += part[t + o]; __syncthreads(); }
    if (t == 0) res_s1 = part[0];
    __syncthreads();
    part[t] = s2;
    __syncthreads();
    for (int o = 512; o; o >>= 1) { if (t < o) part[t] += part[t + o]; __syncthreads(); }
    if (t == 0) res_s2 = part[0];
    __syncthreads();

    if (t == 0) {
        scal[0] = res_z / (float)NTOK;
        float aux = 0.f;
        for (int e = 0; e < NEXP; e++)
            aux += ((float)hist[e] / (float)NTOK) * (cs[e] / (float)NTOK);
        scal[1] = aux * (float)NEXP;
        float inv = 1.f / (float)(NTOK * NEXP);
        float mean = res_s1 * inv;
        float var = res_s2 * inv - mean * mean;
        scal[2] = sqrtf(fmaxf(var, 0.f));
    }
}

// ---------------- launch: read phase -> write phase; finalize hidden --------
extern "C" void kernel_launch(void* const* d_in, const int* in_sizes, int n_in,
                              void* d_out, int out_size) {
    const float* X  = (const float*)d_in[0];
    const float* Wg = (const float*)d_in[1];
    const float* bg = (const float*)d_in[2];
    float* out = (float*)d_out;

    static cudaStream_t s_side = nullptr;
    static cudaEvent_t  ev_rank = nullptr, ev_fin = nullptr;
    if (s_side == nullptr) {
        cudaStreamCreateWithFlags(&s_side, cudaStreamNonBlocking);
        cudaEventCreateWithFlags(&ev_rank, cudaEventDisableTiming);
        cudaEventCreateWithFlags(&ev_fin,  cudaEventDisableTiming);
    }

    // Phase 1 (pure read): gating (+ bucket scatter) then bucket rank
    init_kernel<<<1, 32>>>();
    gating_kernel<<<NTOK, 64>>>(X, Wg, bg, out + LOGITS_OFF);
    rank_kernel<<<NTOK / 8, 256>>>();
    cudaEventRecord(ev_rank, 0);

    // Latency-bound scalar losses overlap the write phase
    cudaStreamWaitEvent(s_side, ev_rank, 0);
    finalize_kernel<<<1, 1024, 0, s_side>>>(out + LOGITS_OFF, out + SCALAR_OFF);
    cudaEventRecord(ev_fin, s_side);

    // Phase 2 (pure write): fused zero-fill + one-hot, 672MB
    writeout_kernel<<<NTOK, 256>>>(out);

    cudaStreamWaitEvent(0, ev_fin, 0);
}

// round 6
// speedup vs baseline: 1.3540x; 1.0543x over previous
#include <cuda_runtime.h>
#include <cstdint>
#include <math.h>

#define NTOK 8192
#define CDIM 64
#define NEXP 16
#define CAP  640
#define NEC  ((size_t)NTOK * NEXP * CAP)       /* 83,886,080 elements */
#define SCALAR_OFF (2 * NEC)                   /* z, aux, std */
#define LOGITS_OFF (2 * NEC + 3)

// ---------------- scratch (no allocs allowed) ----------------
__device__ float              g_probs[NTOK * NEXP];
__device__ float              g_lse2[NTOK];
__device__ unsigned long long g_keys[NTOK];
__device__ int                g_expert[NTOK];
__device__ int                g_bcnt[NEXP];
__device__ unsigned long long g_bkeys[NEXP * NTOK];   // per-expert key buckets (1MB)

// ---------------- kernel 0: zero bucket counters ----------------
__global__ void init_kernel() {
    if (threadIdx.x < NEXP) g_bcnt[threadIdx.x] = 0;
}

// ---------------- kernel 1: pool + gate + softmax + bucket scatter ----------
// one block (64 threads) per token; coalesced reads + smem transpose
__global__ void gating_kernel(const float* __restrict__ X,
                              const float* __restrict__ Wg,
                              const float* __restrict__ bg,
                              float* __restrict__ out_logits) {
    __shared__ float part[64 * 17];   // [channel][lane-in-channel], padded
    __shared__ float pooled[CDIM];
    __shared__ float lg[NEXP];
    const int n = blockIdx.x;
    const int c = threadIdx.x;  // 0..63

    // Coalesced: warp reads 512B contiguous per LDG round.
    const float4* xp = (const float4*)(X + (size_t)n * (CDIM * 64));
#pragma unroll
    for (int i = 0; i < 16; i++) {
        float4 v = xp[i * 64 + c];
        part[(i * 4 + (c >> 4)) * 17 + (c & 15)] = (v.x + v.y) + (v.z + v.w);
    }
    __syncthreads();

    float s = 0.f;
#pragma unroll
    for (int j = 0; j < 16; j++) s += part[c * 17 + j];
    pooled[c] = s * (1.f / 64.f);
    __syncthreads();

    if (c < NEXP) {
        float d = bg[c];
#pragma unroll
        for (int k = 0; k < CDIM; k++) d += pooled[k] * Wg[k * NEXP + c];
        float l = d * (1.f / 1.5f);
        l = fminf(10.f, fmaxf(-10.f, l));
        lg[c] = l;
        out_logits[(size_t)n * NEXP + c] = l;
    }
    __syncthreads();

    if (c < 32) {  // warp 0: softmax/argmax; lanes 0..15 carry data
        float v = (c < 16) ? lg[c] : -3.0e38f;
        float m = v;
        int   mi = c;
#pragma unroll
        for (int o = 8; o; o >>= 1) {
            float om = __shfl_xor_sync(0xffffffffu, m, o);
            int   oi = __shfl_xor_sync(0xffffffffu, mi, o);
            if (om > m || (om == m && oi < mi)) { m = om; mi = oi; }
        }
        float ev = (c < 16) ? expf(v - m) : 0.f;
        float sum = ev;
#pragma unroll
        for (int o = 8; o; o >>= 1) sum += __shfl_xor_sync(0xffffffffu, sum, o);
        if (c < 16) g_probs[n * NEXP + c] = ev / sum;
        if (c == 0) {
            float lse = m + logf(sum);
            g_lse2[n] = lse * lse;
            float pe = 1.f / sum;  // top-1 prob = exp(0)/sum
            g_expert[n] = mi;
            // key: expert (4b) | prob bits (monotonic, positive floats) | 8191-n (stable tie-break)
            unsigned long long key = ((unsigned long long)mi << 45)
                                   | ((unsigned long long)__float_as_uint(pe) << 13)
                                   | (unsigned long long)(8191 - n);
            g_keys[n] = key;
            // bucket scatter (order in bucket irrelevant: rank recomputed by compares)
            int slot = atomicAdd(&g_bcnt[mi], 1);
            g_bkeys[mi * NTOK + slot] = key;
        }
    }
}

// ---------------- kernel 2: fused rank + write-out ----------------
// One block per token: scan own expert's bucket (L2-resident) for rank,
// then emit the token's dispatch & combine slabs (zeros + one hot element).
__global__ void __launch_bounds__(256) writeout_kernel(float* __restrict__ out) {
    __shared__ int s_warp[8];
    __shared__ int s_pos;
    const int n = blockIdx.x;
    const int t = threadIdx.x;

    // inline rank: count strictly-greater keys in this expert's bucket
    const unsigned long long mykey = g_keys[n];
    const int e = g_expert[n];
    const int m = g_bcnt[e];
    const unsigned long long* bk = g_bkeys + (size_t)e * NTOK;
    int cnt = 0;
    for (int j = t; j < m; j += 256) cnt += (int)(bk[j] > mykey);
#pragma unroll
    for (int o = 16; o; o >>= 1) cnt += __shfl_xor_sync(0xffffffffu, cnt, o);
    if ((t & 31) == 0) s_warp[t >> 5] = cnt;
    __syncthreads();
    if (t == 0) {
        int p = 0;
#pragma unroll
        for (int w = 0; w < 8; w++) p += s_warp[w];
        s_pos = p;
    }
    __syncthreads();
    const int pos = s_pos;

    const int hot = (pos < CAP) ? (e * CAP + pos) : -1;
    const int hot_v = hot >> 2;
    const int hot_e = hot & 3;

    float4* dsp = (float4*)(out + (size_t)n * (NEXP * CAP));
    float4* cmb = (float4*)(out + NEC + (size_t)n * (NEXP * CAP));

    const float4 z = make_float4(0.f, 0.f, 0.f, 0.f);
#pragma unroll
    for (int i = 0; i < 10; i++) {
        int idx = t + i * 256;
        float4 v = z;
        if (hot >= 0 && idx == hot_v) ((float*)&v)[hot_e] = 1.f;
        __stcs(&dsp[idx], v);   // streaming (evict-first) stores
        __stcs(&cmb[idx], v);   // combine == dispatch for top-1 routing
    }
}

// ---------------- kernel 3: scalar losses (latency-bound; overlapped) -------
// Depends only on gating outputs: hist[e] = min(bcnt[e], CAP).
__global__ void finalize_kernel(const float* __restrict__ logits,
                                float* __restrict__ scal) {
    __shared__ float part[1024];
    __shared__ float cs[NEXP];
    __shared__ float res_z, res_s1, res_s2;
    int t = threadIdx.x;

    // per-expert prob column sums: thread t only touches column t&15
    float cp = 0.f;
    for (int i = t; i < NTOK * NEXP; i += 1024) cp += g_probs[i];
    part[t] = cp;
    __syncthreads();
    if (t < NEXP) {
        float s = 0.f;
        for (int k = t; k < 1024; k += NEXP) s += part[k];
        cs[t] = s;
    }
    __syncthreads();

    float sz = 0.f;
    for (int i = t; i < NTOK; i += 1024) sz += g_lse2[i];
    part[t] = sz;
    __syncthreads();
    for (int o = 512; o; o >>= 1) { if (t < o) part[t] += part[t + o]; __syncthreads(); }
    if (t == 0) res_z = part[0];
    __syncthreads();

    float s1 = 0.f, s2 = 0.f;
    for (int i = t; i < NTOK * NEXP; i += 1024) {
        float v = logits[i];
        s1 += v; s2 += v * v;
    }
    part[t] = s1;
    __syncthreads();
    for (int o = 512; o; o >>= 1) { if (t < o) part[t] += part[t + o]; __syncthreads(); }
    if (t == 0) res_s1 = part[0];
    __syncthreads();
    part[t] = s2;
    __syncthreads();
    for (int o = 512; o; o >>= 1) { if (t < o) part[t] += part[t + o]; __syncthreads(); }
    if (t == 0) res_s2 = part[0];
    __syncthreads();

    if (t == 0) {
        scal[0] = res_z / (float)NTOK;  // z_loss
        float aux = 0.f;
        for (int e = 0; e < NEXP; e++) {
            int surv = g_bcnt[e] < CAP ? g_bcnt[e] : CAP;  // surviving tokens
            aux += ((float)surv / (float)NTOK) * (cs[e] / (float)NTOK);
        }
        scal[1] = aux * (float)NEXP;    // aux_loss
        float inv = 1.f / (float)(NTOK * NEXP);
        float mean = res_s1 * inv;
        float var = res_s2 * inv - mean * mean;
        scal[2] = sqrtf(fmaxf(var, 0.f));  // logits_std
    }
}

// ---------------- launch ----------------
extern "C" void kernel_launch(void* const* d_in, const int* in_sizes, int n_in,
                              void* d_out, int out_size) {
    const float* X  = (const float*)d_in[0];
    const float* Wg = (const float*)d_in[1];
    const float* bg = (const float*)d_in[2];
    float* out = (float*)d_out;

    static cudaStream_t s_side = nullptr;
    static cudaEvent_t  ev_gate = nullptr, ev_fin = nullptr;
    if (s_side == nullptr) {
        cudaStreamCreateWithFlags(&s_side, cudaStreamNonBlocking);
        cudaEventCreateWithFlags(&ev_gate, cudaEventDisableTiming);
        cudaEventCreateWithFlags(&ev_fin,  cudaEventDisableTiming);
    }

    // Phase 1 (pure read): gating fills keys/buckets/probs/lse2/logits
    init_kernel<<<1, 32>>>();
    gating_kernel<<<NTOK, 64>>>(X, Wg, bg, out + LOGITS_OFF);
    cudaEventRecord(ev_gate, 0);

    // Latency-bound scalar losses fork right after gating (hidden under writes)
    cudaStreamWaitEvent(s_side, ev_gate, 0);
    finalize_kernel<<<1, 1024, 0, s_side>>>(out + LOGITS_OFF, out + SCALAR_OFF);
    cudaEventRecord(ev_fin, s_side);

    // Phase 2 (pure write): fused rank + zero-fill + one-hot, 672MB
    writeout_kernel<<<NTOK, 256>>>(out);

    cudaStreamWaitEvent(0, ev_fin, 0);
}